// round 1
// baseline (speedup 1.0000x reference)
#include <cuda_runtime.h>

#define A_DIM 1024
#define T_DIM 256
#define CS 384
#define CZ 128
#define CA 128
#define CP 16
#define EPS 1e-5f

// ---- device scratch (no allocations allowed) ----
__device__ int   g_tok[A_DIM];
__device__ float g_ys[T_DIM * CA];
__device__ float g_GW[CP * CZ];   // transposed, g-scaled: GW[j][k] = g[k]*Wz[k,j]
__device__ float g_BW[CP];        // sum_k b[k]*Wz[k,j]
__device__ float g_CgW[CP];       // sum_k g[k]*Wz[k,j]
__device__ float g_w[T_DIM * T_DIM * CP];

// ---------------- k0: recover tok[a] from one-hot ----------------
__global__ void k_tok(const float* __restrict__ a2t) {
    int a = blockIdx.x;
    int t = threadIdx.x;
    if (a2t[a * T_DIM + t] > 0.5f) g_tok[a] = t;
}

// ---------------- kP: precompute GW (transposed), BW, CgW ----------------
__global__ void k_pre(const float* __restrict__ g, const float* __restrict__ b,
                      const float* __restrict__ Wz) {
    int tid = threadIdx.x;  // 256 threads
    for (int idx = tid; idx < CP * CZ; idx += 256) {
        int j = idx / CZ, k = idx % CZ;
        g_GW[idx] = g[k] * Wz[k * CP + j];
    }
    if (tid < CP) {
        float bw = 0.f, cg = 0.f;
        for (int k = 0; k < CZ; k++) {
            float w = Wz[k * CP + tid];
            bw += b[k] * w;
            cg += g[k] * w;
        }
        g_BW[tid] = bw;
        g_CgW[tid] = cg;
    }
}

// ---------------- k1: y_s[t,:] = LN(s_trunk[t,:]) @ W_s ----------------
__global__ void k_ys(const float* __restrict__ s_trunk, const float* __restrict__ gk,
                     const float* __restrict__ bk, const float* __restrict__ Ws) {
    __shared__ float sn[CS];
    __shared__ float red[8];
    __shared__ float mv[2];
    int t = blockIdx.x, tid = threadIdx.x;  // 128 threads
    float x0 = s_trunk[t * CS + tid];
    float x1 = s_trunk[t * CS + tid + 128];
    float x2 = s_trunk[t * CS + tid + 256];
    float s1 = x0 + x1 + x2;
    float s2 = x0 * x0 + x1 * x1 + x2 * x2;
    for (int d = 16; d; d >>= 1) {
        s1 += __shfl_down_sync(0xffffffffu, s1, d);
        s2 += __shfl_down_sync(0xffffffffu, s2, d);
    }
    int w = tid >> 5, l = tid & 31;
    if (l == 0) { red[w] = s1; red[4 + w] = s2; }
    __syncthreads();
    if (tid == 0) {
        float S1 = red[0] + red[1] + red[2] + red[3];
        float S2 = red[4] + red[5] + red[6] + red[7];
        float m = S1 / CS;
        float v = S2 / CS - m * m;
        mv[0] = m;
        mv[1] = rsqrtf(v + EPS);
    }
    __syncthreads();
    float m = mv[0], r = mv[1];
    sn[tid]       = (x0 - m) * r * gk[tid]       + bk[tid];
    sn[tid + 128] = (x1 - m) * r * gk[tid + 128] + bk[tid + 128];
    sn[tid + 256] = (x2 - m) * r * gk[tid + 256] + bk[tid + 256];
    __syncthreads();
    float acc = 0.f;
#pragma unroll 8
    for (int k = 0; k < CS; k++) acc = fmaf(sn[k], Ws[k * CA + tid], acc);
    g_ys[t * CA + tid] = acc;
}

// ---------------- k2: cl & ql outputs ----------------
__global__ void k_clql(const float* __restrict__ cl, const float* __restrict__ ql,
                       const float* __restrict__ rl, const float* __restrict__ Wr,
                       float* __restrict__ out_cl, float* __restrict__ out_ql) {
    int a = blockIdx.x, j = threadIdx.x;  // 128 threads
    int ta = g_tok[a];
    out_cl[a * CA + j] = cl[a * CA + j] + g_ys[ta * CA + j];
    float r0 = rl[a * 3], r1 = rl[a * 3 + 1], r2 = rl[a * 3 + 2];
    out_ql[a * CA + j] = ql[a * CA + j]
        + r0 * Wr[j] + r1 * Wr[CA + j] + r2 * Wr[2 * CA + j];
}

// ---------------- k3: w[t,u,:] = LN(zij[t,u,:]) @ W_z ----------------
// Per block: 64 rows (token pairs) x 16 cols, K=128. LN folded:
//   out[r,j] = rinv[r]*(sum_k z[r,k]*GW[j,k] - m[r]*CgW[j]) + BW[j]
#define K3_ROWS 64
#define ZSTRIDE 132   // 128 + 4 pad, keeps 16B alignment, spreads banks

__global__ __launch_bounds__(256) void k_w(const float* __restrict__ zij) {
    __shared__ float Zs[K3_ROWS * ZSTRIDE];
    __shared__ float GWs[CP * ZSTRIDE];
    __shared__ float Ms[K3_ROWS], Rs[K3_ROWS];
    __shared__ float BWs[CP], CgWs[CP];
    int tid = threadIdx.x;
    int row0 = blockIdx.x * K3_ROWS;

    // load Z tile: 64 rows x 128 floats, contiguous => coalesced float4
    const float4* z4 = (const float4*)(zij + (size_t)row0 * CZ);
#pragma unroll
    for (int i = 0; i < 8; i++) {
        int idx = tid + i * 256;          // 0..2047
        int r = idx >> 5, kq = idx & 31;
        float4 v = z4[idx];
        *((float4*)&Zs[r * ZSTRIDE + kq * 4]) = v;
    }
    {
        const float4* gw4 = (const float4*)g_GW;
#pragma unroll
        for (int i = 0; i < 2; i++) {
            int idx = tid + i * 256;      // 0..511
            int j = idx >> 5, kq = idx & 31;
            *((float4*)&GWs[j * ZSTRIDE + kq * 4]) = gw4[idx];
        }
    }
    if (tid < CP) { BWs[tid] = g_BW[tid]; CgWs[tid] = g_CgW[tid]; }
    __syncthreads();

    // stats: 4 threads per row
    {
        int r = tid >> 2, q = tid & 3;
        float s1 = 0.f, s2 = 0.f;
#pragma unroll
        for (int i = 0; i < 32; i++) {
            float v = Zs[r * ZSTRIDE + q + 4 * i];
            s1 += v;
            s2 = fmaf(v, v, s2);
        }
        s1 += __shfl_down_sync(0xffffffffu, s1, 2, 4);
        s2 += __shfl_down_sync(0xffffffffu, s2, 2, 4);
        s1 += __shfl_down_sync(0xffffffffu, s1, 1, 4);
        s2 += __shfl_down_sync(0xffffffffu, s2, 1, 4);
        if (q == 0) {
            float m = s1 * (1.0f / CZ);
            float v = s2 * (1.0f / CZ) - m * m;
            Ms[r] = m;
            Rs[r] = rsqrtf(v + EPS);
        }
    }
    __syncthreads();

    // register-tiled GEMM: thread -> rows (ra,rb), cols (jj, jj+8)
    int jj = tid & 7;
    int rr = tid >> 3;          // 0..31
    int ra = rr * 2, rb = ra + 1;
    float a00 = 0.f, a01 = 0.f, a10 = 0.f, a11 = 0.f;
    const float4* Za = (const float4*)&Zs[ra * ZSTRIDE];
    const float4* Zb = (const float4*)&Zs[rb * ZSTRIDE];
    const float4* G0 = (const float4*)&GWs[jj * ZSTRIDE];
    const float4* G1 = (const float4*)&GWs[(jj + 8) * ZSTRIDE];
#pragma unroll 8
    for (int kq = 0; kq < 32; kq++) {
        float4 za = Za[kq], zb = Zb[kq], w0 = G0[kq], w1 = G1[kq];
        a00 = fmaf(za.x, w0.x, a00); a00 = fmaf(za.y, w0.y, a00);
        a00 = fmaf(za.z, w0.z, a00); a00 = fmaf(za.w, w0.w, a00);
        a01 = fmaf(za.x, w1.x, a01); a01 = fmaf(za.y, w1.y, a01);
        a01 = fmaf(za.z, w1.z, a01); a01 = fmaf(za.w, w1.w, a01);
        a10 = fmaf(zb.x, w0.x, a10); a10 = fmaf(zb.y, w0.y, a10);
        a10 = fmaf(zb.z, w0.z, a10); a10 = fmaf(zb.w, w0.w, a10);
        a11 = fmaf(zb.x, w1.x, a11); a11 = fmaf(zb.y, w1.y, a11);
        a11 = fmaf(zb.z, w1.z, a11); a11 = fmaf(zb.w, w1.w, a11);
    }
    float mA = Ms[ra], rA = Rs[ra], mB = Ms[rb], rB = Rs[rb];
    float c0 = CgWs[jj], c1 = CgWs[jj + 8];
    float b0 = BWs[jj], b1 = BWs[jj + 8];
    float* wout = g_w + (size_t)row0 * CP;
    wout[ra * CP + jj]     = rA * (a00 - mA * c0) + b0;
    wout[ra * CP + jj + 8] = rA * (a01 - mA * c1) + b1;
    wout[rb * CP + jj]     = rB * (a10 - mB * c0) + b0;
    wout[rb * CP + jj + 8] = rB * (a11 - mB * c1) + b1;
}

// ---------------- k4: plm_out[a,b,:] = plm[a,b,:] + w[tok[a],tok[b],:] ----------------
__global__ __launch_bounds__(256) void k_plm(const float* __restrict__ plm,
                                             float* __restrict__ out) {
    int a = blockIdx.y;
    int b = blockIdx.x * 64 + (threadIdx.x >> 2);
    int c4 = threadIdx.x & 3;
    int ta = g_tok[a], tb = g_tok[b];
    size_t pi = ((size_t)a * A_DIM + b) * 4 + c4;
    const float4* p4 = (const float4*)plm;
    const float4* w4 = (const float4*)g_w;
    float4 p = p4[pi];
    float4 w = w4[((size_t)ta * T_DIM + tb) * 4 + c4];
    float4 o;
    o.x = p.x + w.x; o.y = p.y + w.y; o.z = p.z + w.z; o.w = p.w + w.w;
    ((float4*)out)[pi] = o;
}

extern "C" void kernel_launch(void* const* d_in, const int* in_sizes, int n_in,
                              void* d_out, int out_size) {
    const float* a2t     = (const float*)d_in[0];
    const float* cl      = (const float*)d_in[1];
    const float* plm     = (const float*)d_in[2];
    const float* ql      = (const float*)d_in[3];
    const float* s_trunk = (const float*)d_in[4];
    const float* zij     = (const float*)d_in[5];
    const float* rl      = (const float*)d_in[6];
    const float* ln_s_g  = (const float*)d_in[7];
    const float* ln_s_b  = (const float*)d_in[8];
    const float* Ws      = (const float*)d_in[9];
    const float* ln_z_g  = (const float*)d_in[10];
    const float* ln_z_b  = (const float*)d_in[11];
    const float* Wz      = (const float*)d_in[12];
    const float* Wr      = (const float*)d_in[13];
    float* out     = (float*)d_out;
    float* out_cl  = out;
    float* out_plm = out + A_DIM * CA;
    float* out_ql  = out_plm + (size_t)A_DIM * A_DIM * CP;

    k_tok<<<A_DIM, T_DIM>>>(a2t);
    k_pre<<<1, 256>>>(ln_z_g, ln_z_b, Wz);
    k_ys<<<T_DIM, 128>>>(s_trunk, ln_s_g, ln_s_b, Ws);
    k_clql<<<A_DIM, CA>>>(cl, ql, rl, Wr, out_cl, out_ql);
    k_w<<<(T_DIM * T_DIM) / K3_ROWS, 256>>>(zij);
    k_plm<<<dim3(16, A_DIM), 256>>>(plm, out_plm);
}

// round 2
// speedup vs baseline: 1.1760x; 1.1760x over previous
#include <cuda_runtime.h>

#define A_DIM 1024
#define T_DIM 256
#define CS 384
#define CZ 128
#define CA 128
#define CP 16
#define EPS 1e-5f

// ---- device scratch (no allocations allowed) ----
__device__ int   g_tok[A_DIM];
__device__ float g_ys[T_DIM * CA];
__device__ float g_GW[CP * CZ];   // transposed, g-scaled: GW[j][k] = g[k]*Wz[k,j]
__device__ float g_BW[CP];        // sum_k b[k]*Wz[k,j]
__device__ float g_CgW[CP];       // sum_k g[k]*Wz[k,j]
__device__ float g_w[T_DIM * T_DIM * CP];

// ---------------- k_setup: tok recovery + Wz precompute + ys (fused) ----------------
// blocks 0..255: token t = blockIdx.x -> ys row; also scan a2t rows 4t..4t+3 for tok.
// block 256: precompute GW/BW/CgW.
__global__ __launch_bounds__(128) void k_setup(
    const float* __restrict__ a2t, const float* __restrict__ s_trunk,
    const float* __restrict__ gs, const float* __restrict__ bs,
    const float* __restrict__ Ws, const float* __restrict__ gz,
    const float* __restrict__ bz, const float* __restrict__ Wz) {
    int tid = threadIdx.x;
    if (blockIdx.x == T_DIM) {
        // precompute block
        for (int idx = tid; idx < CP * CZ; idx += 128) {
            int j = idx / CZ, k = idx % CZ;
            g_GW[idx] = gz[k] * Wz[k * CP + j];
        }
        if (tid < CP) {
            float bw = 0.f, cg = 0.f;
#pragma unroll 8
            for (int k = 0; k < CZ; k++) {
                float w = Wz[k * CP + tid];
                bw = fmaf(bz[k], w, bw);
                cg = fmaf(gz[k], w, cg);
            }
            g_BW[tid] = bw;
            g_CgW[tid] = cg;
        }
        return;
    }
    int t = blockIdx.x;
    // --- tok recovery for atom rows 4t..4t+3 ---
#pragma unroll
    for (int i = 0; i < 4; i++) {
        int a = t * 4 + i;
        float v0 = a2t[(size_t)a * T_DIM + tid];
        float v1 = a2t[(size_t)a * T_DIM + tid + 128];
        if (v0 > 0.5f) g_tok[a] = tid;
        if (v1 > 0.5f) g_tok[a] = tid + 128;
    }
    // --- ys[t,:] = LN(s_trunk[t,:]) @ W_s ---
    __shared__ float sn[CS];
    __shared__ float red[8];
    __shared__ float mv[2];
    float x0 = s_trunk[t * CS + tid];
    float x1 = s_trunk[t * CS + tid + 128];
    float x2 = s_trunk[t * CS + tid + 256];
    float s1 = x0 + x1 + x2;
    float s2 = x0 * x0 + x1 * x1 + x2 * x2;
    for (int d = 16; d; d >>= 1) {
        s1 += __shfl_down_sync(0xffffffffu, s1, d);
        s2 += __shfl_down_sync(0xffffffffu, s2, d);
    }
    int w = tid >> 5, l = tid & 31;
    if (l == 0) { red[w] = s1; red[4 + w] = s2; }
    __syncthreads();
    if (tid == 0) {
        float S1 = red[0] + red[1] + red[2] + red[3];
        float S2 = red[4] + red[5] + red[6] + red[7];
        float m = S1 / CS;
        float v = S2 / CS - m * m;
        mv[0] = m;
        mv[1] = rsqrtf(v + EPS);
    }
    __syncthreads();
    float m = mv[0], r = mv[1];
    sn[tid]       = (x0 - m) * r * gs[tid]       + bs[tid];
    sn[tid + 128] = (x1 - m) * r * gs[tid + 128] + bs[tid + 128];
    sn[tid + 256] = (x2 - m) * r * gs[tid + 256] + bs[tid + 256];
    __syncthreads();
    float acc = 0.f;
#pragma unroll 8
    for (int k = 0; k < CS; k++) acc = fmaf(sn[k], Ws[k * CA + tid], acc);
    g_ys[t * CA + tid] = acc;
}

// ---------------- k_clql: cl & ql outputs, float4-wide ----------------
__global__ __launch_bounds__(256) void k_clql(
    const float* __restrict__ cl, const float* __restrict__ ql,
    const float* __restrict__ rl, const float* __restrict__ Wr,
    float* __restrict__ out_cl, float* __restrict__ out_ql) {
    int tid = threadIdx.x;
    int a = blockIdx.x * 8 + (tid >> 5);
    int j4 = tid & 31;                 // float4 index within 128-wide row
    int ta = g_tok[a];
    size_t idx = (size_t)a * 32 + j4;
    const float4* cl4 = (const float4*)cl;
    const float4* ql4 = (const float4*)ql;
    const float4* ys4 = (const float4*)g_ys;
    const float4* Wr4 = (const float4*)Wr;
    float4 c = cl4[idx];
    float4 y = ys4[(size_t)ta * 32 + j4];
    float4 q = ql4[idx];
    float r0 = rl[a * 3], r1 = rl[a * 3 + 1], r2 = rl[a * 3 + 2];
    float4 w0 = Wr4[j4], w1 = Wr4[32 + j4], w2 = Wr4[64 + j4];
    float4 oc, oq;
    oc.x = c.x + y.x; oc.y = c.y + y.y; oc.z = c.z + y.z; oc.w = c.w + y.w;
    oq.x = q.x + r0 * w0.x + r1 * w1.x + r2 * w2.x;
    oq.y = q.y + r0 * w0.y + r1 * w1.y + r2 * w2.y;
    oq.z = q.z + r0 * w0.z + r1 * w1.z + r2 * w2.z;
    oq.w = q.w + r0 * w0.w + r1 * w1.w + r2 * w2.w;
    ((float4*)out_cl)[idx] = oc;
    ((float4*)out_ql)[idx] = oq;
}

// ---------------- k_w: w[t,u,:] = LN(zij[t,u,:]) @ W_z ----------------
#define K3_ROWS 64
#define ZSTRIDE 132   // 128 + 4 pad

__global__ __launch_bounds__(256) void k_w(const float* __restrict__ zij) {
    __shared__ float Zs[K3_ROWS * ZSTRIDE];
    __shared__ float GWs[CP * ZSTRIDE];
    __shared__ float Ms[K3_ROWS], Rs[K3_ROWS];
    __shared__ float BWs[CP], CgWs[CP];
    int tid = threadIdx.x;
    int row0 = blockIdx.x * K3_ROWS;

    const float4* z4 = (const float4*)(zij + (size_t)row0 * CZ);
#pragma unroll
    for (int i = 0; i < 8; i++) {
        int idx = tid + i * 256;
        int r = idx >> 5, kq = idx & 31;
        float4 v = z4[idx];
        *((float4*)&Zs[r * ZSTRIDE + kq * 4]) = v;
    }
    {
        const float4* gw4 = (const float4*)g_GW;
#pragma unroll
        for (int i = 0; i < 2; i++) {
            int idx = tid + i * 256;
            int j = idx >> 5, kq = idx & 31;
            *((float4*)&GWs[j * ZSTRIDE + kq * 4]) = gw4[idx];
        }
    }
    if (tid < CP) { BWs[tid] = g_BW[tid]; CgWs[tid] = g_CgW[tid]; }
    __syncthreads();

    // stats: 4 threads per row
    {
        int r = tid >> 2, q = tid & 3;
        float s1 = 0.f, s2 = 0.f;
#pragma unroll
        for (int i = 0; i < 32; i++) {
            float v = Zs[r * ZSTRIDE + q + 4 * i];
            s1 += v;
            s2 = fmaf(v, v, s2);
        }
        s1 += __shfl_down_sync(0xffffffffu, s1, 2, 4);
        s2 += __shfl_down_sync(0xffffffffu, s2, 2, 4);
        s1 += __shfl_down_sync(0xffffffffu, s1, 1, 4);
        s2 += __shfl_down_sync(0xffffffffu, s2, 1, 4);
        if (q == 0) {
            float m = s1 * (1.0f / CZ);
            float v = s2 * (1.0f / CZ) - m * m;
            Ms[r] = m;
            Rs[r] = rsqrtf(v + EPS);
        }
    }
    __syncthreads();

    int jj = tid & 7;
    int rr = tid >> 3;
    int ra = rr * 2, rb = ra + 1;
    float a00 = 0.f, a01 = 0.f, a10 = 0.f, a11 = 0.f;
    const float4* Za = (const float4*)&Zs[ra * ZSTRIDE];
    const float4* Zb = (const float4*)&Zs[rb * ZSTRIDE];
    const float4* G0 = (const float4*)&GWs[jj * ZSTRIDE];
    const float4* G1 = (const float4*)&GWs[(jj + 8) * ZSTRIDE];
#pragma unroll 8
    for (int kq = 0; kq < 32; kq++) {
        float4 za = Za[kq], zb = Zb[kq], w0 = G0[kq], w1 = G1[kq];
        a00 = fmaf(za.x, w0.x, a00); a00 = fmaf(za.y, w0.y, a00);
        a00 = fmaf(za.z, w0.z, a00); a00 = fmaf(za.w, w0.w, a00);
        a01 = fmaf(za.x, w1.x, a01); a01 = fmaf(za.y, w1.y, a01);
        a01 = fmaf(za.z, w1.z, a01); a01 = fmaf(za.w, w1.w, a01);
        a10 = fmaf(zb.x, w0.x, a10); a10 = fmaf(zb.y, w0.y, a10);
        a10 = fmaf(zb.z, w0.z, a10); a10 = fmaf(zb.w, w0.w, a10);
        a11 = fmaf(zb.x, w1.x, a11); a11 = fmaf(zb.y, w1.y, a11);
        a11 = fmaf(zb.z, w1.z, a11); a11 = fmaf(zb.w, w1.w, a11);
    }
    float mA = Ms[ra], rA = Rs[ra], mB = Ms[rb], rB = Rs[rb];
    float c0 = CgWs[jj], c1 = CgWs[jj + 8];
    float b0 = BWs[jj], b1 = BWs[jj + 8];
    float* wout = g_w + (size_t)row0 * CP;
    wout[ra * CP + jj]     = rA * (a00 - mA * c0) + b0;
    wout[ra * CP + jj + 8] = rA * (a01 - mA * c1) + b1;
    wout[rb * CP + jj]     = rB * (a10 - mB * c0) + b0;
    wout[rb * CP + jj + 8] = rB * (a11 - mB * c1) + b1;
}

// ---------------- k_plm: plm_out[a,b,:] = plm[a,b,:] + w[tok[a],tok[b],:] ----------------
// 4 a-rows per thread for MLP; fully coalesced 16B lanes.
__global__ __launch_bounds__(256) void k_plm(const float* __restrict__ plm,
                                             float* __restrict__ out) {
    int tid = threadIdx.x;
    int a0 = blockIdx.y * 4;
    int b = blockIdx.x * 64 + (tid >> 2);
    int c4 = tid & 3;
    int tb = g_tok[b];
    const float4* p4 = (const float4*)plm;
    const float4* w4 = (const float4*)g_w;
    float4* o4 = (float4*)out;

    int ta[4];
#pragma unroll
    for (int i = 0; i < 4; i++) ta[i] = g_tok[a0 + i];

    float4 p[4], w[4];
#pragma unroll
    for (int i = 0; i < 4; i++)
        p[i] = p4[((size_t)(a0 + i) * A_DIM + b) * 4 + c4];
#pragma unroll
    for (int i = 0; i < 4; i++)
        w[i] = w4[((size_t)ta[i] * T_DIM + tb) * 4 + c4];
#pragma unroll
    for (int i = 0; i < 4; i++) {
        float4 o;
        o.x = p[i].x + w[i].x; o.y = p[i].y + w[i].y;
        o.z = p[i].z + w[i].z; o.w = p[i].w + w[i].w;
        o4[((size_t)(a0 + i) * A_DIM + b) * 4 + c4] = o;
    }
}

extern "C" void kernel_launch(void* const* d_in, const int* in_sizes, int n_in,
                              void* d_out, int out_size) {
    const float* a2t     = (const float*)d_in[0];
    const float* cl      = (const float*)d_in[1];
    const float* plm     = (const float*)d_in[2];
    const float* ql      = (const float*)d_in[3];
    const float* s_trunk = (const float*)d_in[4];
    const float* zij     = (const float*)d_in[5];
    const float* rl      = (const float*)d_in[6];
    const float* ln_s_g  = (const float*)d_in[7];
    const float* ln_s_b  = (const float*)d_in[8];
    const float* Ws      = (const float*)d_in[9];
    const float* ln_z_g  = (const float*)d_in[10];
    const float* ln_z_b  = (const float*)d_in[11];
    const float* Wz      = (const float*)d_in[12];
    const float* Wr      = (const float*)d_in[13];
    float* out     = (float*)d_out;
    float* out_cl  = out;
    float* out_plm = out + A_DIM * CA;
    float* out_ql  = out_plm + (size_t)A_DIM * A_DIM * CP;

    k_setup<<<T_DIM + 1, 128>>>(a2t, s_trunk, ln_s_g, ln_s_b, Ws,
                                ln_z_g, ln_z_b, Wz);
    k_w<<<(T_DIM * T_DIM) / K3_ROWS, 256>>>(zij);
    k_clql<<<A_DIM / 8, 256>>>(cl, ql, rl, Wr, out_cl, out_ql);
    k_plm<<<dim3(16, A_DIM / 4), 256>>>(plm, out_plm);
}